// round 13
// baseline (speedup 1.0000x reference)
#include <cuda_runtime.h>
#include <cstdint>

#define N_NODES 2048
#define IN_DIM 32
#define LATENT 64

typedef unsigned long long ull;

// Scratch (__device__ globals: allocation-free rule)
__device__ float  g_zaT[LATENT * N_NODES];  // [l][n]: zi transposed
__device__ float  g_zbT[LATENT * N_NODES];  // [l][n]: zjb transposed
__device__ float2 g_wsd[LATENT];            // 0.495*w, duplicated
__device__ float  g_aw2[N_NODES];           // 0.505 * dot(w, zi[i])
__device__ float  g_cw2[N_NODES];           // 0.505 * dot(w, zjb[j]) + b_e2

// ---------------------------------------------------------------------------
// Kernel 1: per-node precompute, 16 nodes/block -> 128 blocks (single wave).
// ---------------------------------------------------------------------------
__global__ __launch_bounds__(256) void node_precompute_kernel(
    const float* __restrict__ x,
    const float* __restrict__ W_ne, const float* __restrict__ b_ne,
    const float* __restrict__ W_e1a, const float* __restrict__ W_e1b,
    const float* __restrict__ b_e1,
    const float* __restrict__ w_e2, const float* __restrict__ b_e2)
{
    __shared__ float sWne[IN_DIM * LATENT];
    __shared__ float sWa[LATENT * LATENT];
    __shared__ float sWb[LATENT * LATENT];
    __shared__ float sx[16][IN_DIM];
    __shared__ float sz[16][LATENT];
    __shared__ float szi[16][LATENT];
    __shared__ float szjb[16][LATENT];

    const int tid = threadIdx.x;
    const int nb = blockIdx.x * 16;

    for (int i = tid; i < IN_DIM * LATENT / 4; i += 256)
        ((float4*)sWne)[i] = ((const float4*)W_ne)[i];
    for (int i = tid; i < LATENT * LATENT / 4; i += 256) {
        ((float4*)sWa)[i] = ((const float4*)W_e1a)[i];
        ((float4*)sWb)[i] = ((const float4*)W_e1b)[i];
    }
    if (tid < 128)
        ((float4*)sx)[tid] = ((const float4*)&x[nb * IN_DIM])[tid];
    __syncthreads();

#pragma unroll
    for (int r = 0; r < 4; r++) {
        int idx = tid + 256 * r;
        int n = idx >> 6, l = idx & 63;
        float acc = b_ne[l];
#pragma unroll
        for (int k = 0; k < IN_DIM; k++)
            acc = fmaf(sx[n][k], sWne[k * LATENT + l], acc);
        sz[n][l] = fmaxf(acc, 0.01f * acc);
    }
    __syncthreads();

#pragma unroll
    for (int r = 0; r < 4; r++) {
        int idx = tid + 256 * r;
        int n = idx >> 6, l = idx & 63;
        float zi_v = 0.0f;
        float zjb_v = b_e1[l];
#pragma unroll
        for (int k4 = 0; k4 < LATENT / 4; k4++) {
            const float4 z4 = *(const float4*)&sz[n][k4 * 4];  // warp-broadcast
            zi_v  = fmaf(z4.x, sWa[(k4 * 4 + 0) * LATENT + l], zi_v);
            zjb_v = fmaf(z4.x, sWb[(k4 * 4 + 0) * LATENT + l], zjb_v);
            zi_v  = fmaf(z4.y, sWa[(k4 * 4 + 1) * LATENT + l], zi_v);
            zjb_v = fmaf(z4.y, sWb[(k4 * 4 + 1) * LATENT + l], zjb_v);
            zi_v  = fmaf(z4.z, sWa[(k4 * 4 + 2) * LATENT + l], zi_v);
            zjb_v = fmaf(z4.z, sWb[(k4 * 4 + 2) * LATENT + l], zjb_v);
            zi_v  = fmaf(z4.w, sWa[(k4 * 4 + 3) * LATENT + l], zi_v);
            zjb_v = fmaf(z4.w, sWb[(k4 * 4 + 3) * LATENT + l], zjb_v);
        }
        szi[n][l] = zi_v;
        szjb[n][l] = zjb_v;
        g_zaT[l * N_NODES + nb + n] = zi_v;   // transposed scatter (tiny volume)
        g_zbT[l * N_NODES + nb + n] = zjb_v;
    }
    __syncthreads();

    const int wid = tid >> 5, lane = tid & 31;
    const float w1 = w_e2[lane], w2 = w_e2[lane + 32];
#pragma unroll
    for (int s = 0; s < 2; s++) {
        const int n = 2 * wid + s;
        float s1 = w1 * szi[n][lane]  + w2 * szi[n][lane + 32];
        float s2 = w1 * szjb[n][lane] + w2 * szjb[n][lane + 32];
#pragma unroll
        for (int off = 16; off > 0; off >>= 1) {
            s1 += __shfl_down_sync(0xffffffffu, s1, off);
            s2 += __shfl_down_sync(0xffffffffu, s2, off);
        }
        if (lane == 0) {
            g_aw2[nb + n] = 0.505f * s1;
            g_cw2[nb + n] = 0.505f * s2 + b_e2[0];
        }
    }
    if (blockIdx.x == 0 && tid < LATENT) {
        float w = 0.495f * w_e2[tid];
        g_wsd[tid] = make_float2(w, w);
    }
}

// ---------------------------------------------------------------------------
// Kernel 2: 32i x 64j tile, 256 threads, 2i x 4j outputs/thread, 7 blocks/SM.
// Max-occupancy variant: 25.5KB smem, <=36 regs, 87.5% theoretical occ.
// Per latent/thread: LDS64 w + LDS64 a + LDS128 b + 2 MOV;
// math: add2 + packed-abs AND + fma2-accumulate.
// logit(i,j) = aw2[i] + cw2[j] + sum_l ws[l] * |zi[i,l] + zjb[j,l]|
// out = (sigmoid(logit) + 1e-8) * exp(gumbel)
// ---------------------------------------------------------------------------
__global__ __launch_bounds__(256, 7) void edge_prob_kernel(
    const float* __restrict__ gumbel, float* __restrict__ out)
{
    extern __shared__ char smem_raw[];
    float*  s_aT  = (float*)smem_raw;                    // [64][32]    8192B
    float*  s_b   = (float*)(smem_raw + 8192);           // [64][64]   16384B
    float2* s_wsd = (float2*)(smem_raw + 24576);         // [64] dup     512B
    float*  s_aw  = (float*)(smem_raw + 25088);          // [32]         128B
    float*  s_cw  = (float*)(smem_raw + 25216);          // [64]         256B

    const int tid = threadIdx.x;
    const int ibase = blockIdx.y * 32;
    const int jbase = blockIdx.x * 64;

    // load phase (coalesced float4)
#pragma unroll
    for (int t = tid; t < 512; t += 256) {
        int r = t >> 3, c4 = (t & 7) * 4;
        *(float4*)&s_aT[r * 32 + c4] =
            *(const float4*)&g_zaT[(size_t)r * N_NODES + ibase + c4];
    }
#pragma unroll
    for (int t = tid; t < 1024; t += 256) {
        int r = t >> 4, c4 = (t & 15) * 4;
        *(float4*)&s_b[r * 64 + c4] =
            *(const float4*)&g_zbT[(size_t)r * N_NODES + jbase + c4];
    }
    if (tid < 64) s_wsd[tid] = g_wsd[tid];
    if (tid < 32) s_aw[tid] = g_aw2[ibase + tid];
    if (tid >= 64 && tid < 128) s_cw[tid - 64] = g_cw2[jbase + tid - 64];
    __syncthreads();

    const int tx = tid & 15;   // j: cols tx*4..+3
    const int ty = tid >> 4;   // i: rows ty*2..+1
    const int arow = ty * 2;

    ull acc[2][2];
    acc[0][0] = acc[0][1] = acc[1][0] = acc[1][1] = 0ull;

    const ull ABSM = 0x7fffffff7fffffffULL;

#pragma unroll 2
    for (int l = 0; l < LATENT; l++) {
        const ull wv = *(const ull*)&s_wsd[l];                  // dup (w,w)
        const float2 a2 = *(const float2*)&s_aT[l * 32 + arow]; // 2 i-values
        ull b[2];
        {
            ulonglong2 t0 = *(const ulonglong2*)&s_b[l * 64 + tx * 4];
            b[0] = t0.x; b[1] = t0.y;
        }
        const float af[2] = {a2.x, a2.y};
#pragma unroll
        for (int ii = 0; ii < 2; ii++) {
            ull ap;
            {
                unsigned r0 = __float_as_uint(af[ii]);
                asm("mov.b64 %0, {%1, %1};" : "=l"(ap) : "r"(r0));
            }
#pragma unroll
            for (int q = 0; q < 2; q++) {
                ull v;
                asm("add.rn.f32x2 %0, %1, %2;" : "=l"(v) : "l"(ap), "l"(b[q]));
                v &= ABSM;                                      // packed abs
                asm("fma.rn.f32x2 %0, %1, %2, %3;"
                    : "=l"(acc[ii][q]) : "l"(wv), "l"(v), "l"(acc[ii][q]));
            }
        }
    }

    // epilogue
#pragma unroll
    for (int ii = 0; ii < 2; ii++) {
        const int il = arow + ii;
        const int i = ibase + il;
        const float base_i = s_aw[il];
        const int jl = tx * 4;
        const size_t off = (size_t)i * N_NODES + jbase + jl;
        const float4 gv = *(const float4*)&gumbel[off];
        const float g4[4] = {gv.x, gv.y, gv.z, gv.w};

        float accf[4];
#pragma unroll
        for (int p = 0; p < 2; p++) {
            unsigned lo, hi;
            asm("mov.b64 {%0, %1}, %2;" : "=r"(lo), "=r"(hi) : "l"(acc[ii][p]));
            accf[p * 2 + 0] = __uint_as_float(lo);
            accf[p * 2 + 1] = __uint_as_float(hi);
        }

        float4 o;
        float* op = &o.x;
#pragma unroll
        for (int jj = 0; jj < 4; jj++) {
            float logit = accf[jj] + base_i + s_cw[jl + jj];
            float e = __expf(-logit);
            float p = __fdividef(1.0f, 1.0f + e);
            op[jj] = (p + 1e-8f) * __expf(g4[jj]);
        }
        *(float4*)&out[off] = o;
    }
}

// ---------------------------------------------------------------------------
// Inputs (metadata order):
// 0:x [N,32] 1:in_adj [N,N](unused) 2:gumbel [N,N] 3:W_ne [32,64] 4:b_ne [64]
// 5:W_e1a [64,64] 6:W_e1b [64,64] 7:b_e1 [64] 8:w_e2 [64] 9:b_e2 []
// out: [N,N] float32
// ---------------------------------------------------------------------------
extern "C" void kernel_launch(void* const* d_in, const int* in_sizes, int n_in,
                              void* d_out, int out_size)
{
    const float* x      = (const float*)d_in[0];
    const float* gumbel = (const float*)d_in[2];
    const float* W_ne   = (const float*)d_in[3];
    const float* b_ne   = (const float*)d_in[4];
    const float* W_e1a  = (const float*)d_in[5];
    const float* W_e1b  = (const float*)d_in[6];
    const float* b_e1   = (const float*)d_in[7];
    const float* w_e2   = (const float*)d_in[8];
    const float* b_e2   = (const float*)d_in[9];
    float* out = (float*)d_out;

    node_precompute_kernel<<<N_NODES / 16, 256>>>(x, W_ne, b_ne, W_e1a, W_e1b,
                                                  b_e1, w_e2, b_e2);

    static bool attr_set = false;
    if (!attr_set) {
        cudaFuncSetAttribute(edge_prob_kernel,
                             cudaFuncAttributeMaxDynamicSharedMemorySize, 25472);
        attr_set = true;
    }
    dim3 grid(N_NODES / 64, N_NODES / 32);
    edge_prob_kernel<<<grid, 256, 25472>>>(gumbel, out);
}

// round 14
// speedup vs baseline: 1.0951x; 1.0951x over previous
#include <cuda_runtime.h>
#include <cstdint>

#define N_NODES 2048
#define IN_DIM 32
#define LATENT 64

typedef unsigned long long ull;

// Scratch (__device__ globals: allocation-free rule)
__device__ float  g_zadT[LATENT * 2 * N_NODES]; // [l][2n]: dup pairs (v,v) of zi, transposed
__device__ float  g_zbT[LATENT * N_NODES];      // [l][n]: zjb transposed
__device__ float2 g_wsd[LATENT];                // 0.495*w, duplicated
__device__ float  g_aw2[N_NODES];               // 0.505 * dot(w, zi[i])
__device__ float  g_cw2[N_NODES];               // 0.505 * dot(w, zjb[j]) + b_e2

// ---------------------------------------------------------------------------
// Kernel 1: per-node precompute, 16 nodes/block -> 128 blocks (single wave).
// ---------------------------------------------------------------------------
__global__ __launch_bounds__(256) void node_precompute_kernel(
    const float* __restrict__ x,
    const float* __restrict__ W_ne, const float* __restrict__ b_ne,
    const float* __restrict__ W_e1a, const float* __restrict__ W_e1b,
    const float* __restrict__ b_e1,
    const float* __restrict__ w_e2, const float* __restrict__ b_e2)
{
    __shared__ float sWne[IN_DIM * LATENT];
    __shared__ float sWa[LATENT * LATENT];
    __shared__ float sWb[LATENT * LATENT];
    __shared__ float sx[16][IN_DIM];
    __shared__ float sz[16][LATENT];
    __shared__ float szi[16][LATENT];
    __shared__ float szjb[16][LATENT];

    const int tid = threadIdx.x;
    const int nb = blockIdx.x * 16;

    for (int i = tid; i < IN_DIM * LATENT / 4; i += 256)
        ((float4*)sWne)[i] = ((const float4*)W_ne)[i];
    for (int i = tid; i < LATENT * LATENT / 4; i += 256) {
        ((float4*)sWa)[i] = ((const float4*)W_e1a)[i];
        ((float4*)sWb)[i] = ((const float4*)W_e1b)[i];
    }
    if (tid < 128)
        ((float4*)sx)[tid] = ((const float4*)&x[nb * IN_DIM])[tid];
    __syncthreads();

#pragma unroll
    for (int r = 0; r < 4; r++) {
        int idx = tid + 256 * r;
        int n = idx >> 6, l = idx & 63;
        float acc = b_ne[l];
#pragma unroll
        for (int k = 0; k < IN_DIM; k++)
            acc = fmaf(sx[n][k], sWne[k * LATENT + l], acc);
        sz[n][l] = fmaxf(acc, 0.01f * acc);
    }
    __syncthreads();

#pragma unroll
    for (int r = 0; r < 4; r++) {
        int idx = tid + 256 * r;
        int n = idx >> 6, l = idx & 63;
        float zi_v = 0.0f;
        float zjb_v = b_e1[l];
#pragma unroll
        for (int k4 = 0; k4 < LATENT / 4; k4++) {
            const float4 z4 = *(const float4*)&sz[n][k4 * 4];  // warp-broadcast
            zi_v  = fmaf(z4.x, sWa[(k4 * 4 + 0) * LATENT + l], zi_v);
            zjb_v = fmaf(z4.x, sWb[(k4 * 4 + 0) * LATENT + l], zjb_v);
            zi_v  = fmaf(z4.y, sWa[(k4 * 4 + 1) * LATENT + l], zi_v);
            zjb_v = fmaf(z4.y, sWb[(k4 * 4 + 1) * LATENT + l], zjb_v);
            zi_v  = fmaf(z4.z, sWa[(k4 * 4 + 2) * LATENT + l], zi_v);
            zjb_v = fmaf(z4.z, sWb[(k4 * 4 + 2) * LATENT + l], zjb_v);
            zi_v  = fmaf(z4.w, sWa[(k4 * 4 + 3) * LATENT + l], zi_v);
            zjb_v = fmaf(z4.w, sWb[(k4 * 4 + 3) * LATENT + l], zjb_v);
        }
        szi[n][l] = zi_v;
        szjb[n][l] = zjb_v;
        // dup-pair transposed scatter (8B store) + zjb transposed scatter
        ((float2*)g_zadT)[(size_t)l * N_NODES + nb + n] = make_float2(zi_v, zi_v);
        g_zbT[(size_t)l * N_NODES + nb + n] = zjb_v;
    }
    __syncthreads();

    const int wid = tid >> 5, lane = tid & 31;
    const float w1 = w_e2[lane], w2 = w_e2[lane + 32];
#pragma unroll
    for (int s = 0; s < 2; s++) {
        const int n = 2 * wid + s;
        float s1 = w1 * szi[n][lane]  + w2 * szi[n][lane + 32];
        float s2 = w1 * szjb[n][lane] + w2 * szjb[n][lane + 32];
#pragma unroll
        for (int off = 16; off > 0; off >>= 1) {
            s1 += __shfl_down_sync(0xffffffffu, s1, off);
            s2 += __shfl_down_sync(0xffffffffu, s2, off);
        }
        if (lane == 0) {
            g_aw2[nb + n] = 0.505f * s1;
            g_cw2[nb + n] = 0.505f * s2 + b_e2[0];
        }
    }
    if (blockIdx.x == 0 && tid < LATENT) {
        float w = 0.495f * w_e2[tid];
        g_wsd[tid] = make_float2(w, w);
    }
}

// ---------------------------------------------------------------------------
// Kernel 2: 32i x 128j tile, 256 threads, 2i x 8j outputs/thread, 4 blocks/SM,
// grid 1024. Per latent/thread: LDS64 w + LDS128 a-dup (both i pairs, no MOV)
// + 2x LDS128 b; math: add2 + packed-abs AND + fma2-accumulate. iPM ~2.25.
// logit(i,j) = aw2[i] + cw2[j] + sum_l ws[l] * |zi[i,l] + zjb[j,l]|
// out = (sigmoid(logit) + 1e-8) * exp(gumbel)
// ---------------------------------------------------------------------------
__global__ __launch_bounds__(256, 4) void edge_prob_kernel(
    const float* __restrict__ gumbel, float* __restrict__ out)
{
    extern __shared__ char smem_raw[];
    float*  s_ad  = (float*)smem_raw;                    // [64][64] dup  16384B
    float*  s_b   = (float*)(smem_raw + 16384);          // [64][128]    32768B
    float2* s_wsd = (float2*)(smem_raw + 49152);         // [64] dup       512B
    float*  s_aw  = (float*)(smem_raw + 49664);          // [32]           128B
    float*  s_cw  = (float*)(smem_raw + 49792);          // [128]          512B

    const int tid = threadIdx.x;
    const int ibase = blockIdx.y * 32;
    const int jbase = blockIdx.x * 128;

    // load phase (coalesced float4)
#pragma unroll
    for (int t = tid; t < 1024; t += 256) {
        int r = t >> 4, c4 = (t & 15) * 4;   // r: latent, c4: dup-float col
        *(float4*)&s_ad[r * 64 + c4] =
            *(const float4*)&g_zadT[(size_t)r * (2 * N_NODES) + 2 * ibase + c4];
    }
#pragma unroll
    for (int t = tid; t < 2048; t += 256) {
        int r = t >> 5, c4 = (t & 31) * 4;
        *(float4*)&s_b[r * 128 + c4] =
            *(const float4*)&g_zbT[(size_t)r * N_NODES + jbase + c4];
    }
    if (tid < 64) s_wsd[tid] = g_wsd[tid];
    if (tid < 32) s_aw[tid] = g_aw2[ibase + tid];
    if (tid >= 64 && tid < 192) s_cw[tid - 64] = g_cw2[jbase + tid - 64];
    __syncthreads();

    const int tx = tid & 15;   // j: cols tx*4..+3 and 64+tx*4..+3
    const int ty = tid >> 4;   // i: rows ty*2..+1
    const int arow = ty * 2;

    ull acc[2][4];             // [ii][q]: q 0-1 -> j group 0, q 2-3 -> group 1
#pragma unroll
    for (int ii = 0; ii < 2; ii++)
#pragma unroll
        for (int q = 0; q < 4; q++) acc[ii][q] = 0ull;

    const ull ABSM = 0x7fffffff7fffffffULL;

#pragma unroll 4
    for (int l = 0; l < LATENT; l++) {
        const ull wv = *(const ull*)&s_wsd[l];           // dup (w,w): LDS64
        ull ad[2];                                       // dup pairs for i0,i1
        {
            ulonglong2 t0 = *(const ulonglong2*)&s_ad[l * 64 + arow * 2];
            ad[0] = t0.x; ad[1] = t0.y;                  // one LDS128, no MOV
        }
        ull b[4];
        {
            ulonglong2 t0 = *(const ulonglong2*)&s_b[l * 128 + tx * 4];
            ulonglong2 t1 = *(const ulonglong2*)&s_b[l * 128 + 64 + tx * 4];
            b[0] = t0.x; b[1] = t0.y; b[2] = t1.x; b[3] = t1.y;
        }
#pragma unroll
        for (int ii = 0; ii < 2; ii++) {
#pragma unroll
            for (int q = 0; q < 4; q++) {
                ull v;
                asm("add.rn.f32x2 %0, %1, %2;" : "=l"(v) : "l"(ad[ii]), "l"(b[q]));
                v &= ABSM;                                // packed abs
                asm("fma.rn.f32x2 %0, %1, %2, %3;"
                    : "=l"(acc[ii][q]) : "l"(wv), "l"(v), "l"(acc[ii][q]));
            }
        }
    }

    // epilogue
#pragma unroll
    for (int ii = 0; ii < 2; ii++) {
        const int il = arow + ii;
        const int i = ibase + il;
        const float base_i = s_aw[il];
#pragma unroll
        for (int g = 0; g < 2; g++) {
            const int jl = g * 64 + tx * 4;
            const size_t off = (size_t)i * N_NODES + jbase + jl;
            const float4 gv = *(const float4*)&gumbel[off];
            const float g4[4] = {gv.x, gv.y, gv.z, gv.w};

            float accf[4];
#pragma unroll
            for (int p = 0; p < 2; p++) {
                unsigned lo, hi;
                asm("mov.b64 {%0, %1}, %2;" : "=r"(lo), "=r"(hi)
                    : "l"(acc[ii][g * 2 + p]));
                accf[p * 2 + 0] = __uint_as_float(lo);
                accf[p * 2 + 1] = __uint_as_float(hi);
            }

            float4 o;
            float* op = &o.x;
#pragma unroll
            for (int jj = 0; jj < 4; jj++) {
                float logit = accf[jj] + base_i + s_cw[jl + jj];
                float e = __expf(-logit);
                float p = __fdividef(1.0f, 1.0f + e);
                op[jj] = (p + 1e-8f) * __expf(g4[jj]);
            }
            *(float4*)&out[off] = o;
        }
    }
}

// ---------------------------------------------------------------------------
// Inputs (metadata order):
// 0:x [N,32] 1:in_adj [N,N](unused) 2:gumbel [N,N] 3:W_ne [32,64] 4:b_ne [64]
// 5:W_e1a [64,64] 6:W_e1b [64,64] 7:b_e1 [64] 8:w_e2 [64] 9:b_e2 []
// out: [N,N] float32
// ---------------------------------------------------------------------------
extern "C" void kernel_launch(void* const* d_in, const int* in_sizes, int n_in,
                              void* d_out, int out_size)
{
    const float* x      = (const float*)d_in[0];
    const float* gumbel = (const float*)d_in[2];
    const float* W_ne   = (const float*)d_in[3];
    const float* b_ne   = (const float*)d_in[4];
    const float* W_e1a  = (const float*)d_in[5];
    const float* W_e1b  = (const float*)d_in[6];
    const float* b_e1   = (const float*)d_in[7];
    const float* w_e2   = (const float*)d_in[8];
    const float* b_e2   = (const float*)d_in[9];
    float* out = (float*)d_out;

    node_precompute_kernel<<<N_NODES / 16, 256>>>(x, W_ne, b_ne, W_e1a, W_e1b,
                                                  b_e1, w_e2, b_e2);

    static bool attr_set = false;
    if (!attr_set) {
        cudaFuncSetAttribute(edge_prob_kernel,
                             cudaFuncAttributeMaxDynamicSharedMemorySize, 50304);
        attr_set = true;
    }
    dim3 grid(N_NODES / 128, N_NODES / 32);
    edge_prob_kernel<<<grid, 256, 50304>>>(gumbel, out);
}

// round 15
// speedup vs baseline: 1.3731x; 1.2538x over previous
#include <cuda_runtime.h>
#include <cstdint>

#define N_NODES 2048
#define IN_DIM 32
#define LATENT 64
#define PADT 68    // tile row stride (floats); 272B, 16B-aligned

// Scratch (__device__ globals: allocation-free rule)
__device__ float g_zi[N_NODES * LATENT];    // [n][l]
__device__ float g_zbT[LATENT * N_NODES];   // [l][n] transposed
__device__ float g_ws[LATENT];              // 0.495 * w
__device__ float g_aw2[N_NODES];            // 0.505 * dot(w, zi[i])
__device__ float g_cw2[N_NODES];            // 0.505 * dot(w, zjb[j]) + b_e2

// ---------------------------------------------------------------------------
// Kernel 1: per-node precompute, 16 nodes/block -> 128 blocks (single wave).
// Phase 2 vectorized: 4 latents/thread with float4 weight loads.
// ---------------------------------------------------------------------------
__global__ __launch_bounds__(256) void node_precompute_kernel(
    const float* __restrict__ x,
    const float* __restrict__ W_ne, const float* __restrict__ b_ne,
    const float* __restrict__ W_e1a, const float* __restrict__ W_e1b,
    const float* __restrict__ b_e1,
    const float* __restrict__ w_e2, const float* __restrict__ b_e2)
{
    __shared__ float sWne[IN_DIM * LATENT];
    __shared__ float sWa[LATENT * LATENT];
    __shared__ float sWb[LATENT * LATENT];
    __shared__ float sx[16][IN_DIM];
    __shared__ float sz[16][LATENT];
    __shared__ float szi[16][LATENT];
    __shared__ float szjb[16][LATENT];

    const int tid = threadIdx.x;
    const int nb = blockIdx.x * 16;

    for (int i = tid; i < IN_DIM * LATENT / 4; i += 256)
        ((float4*)sWne)[i] = ((const float4*)W_ne)[i];
    for (int i = tid; i < LATENT * LATENT / 4; i += 256) {
        ((float4*)sWa)[i] = ((const float4*)W_e1a)[i];
        ((float4*)sWb)[i] = ((const float4*)W_e1b)[i];
    }
    if (tid < 128)
        ((float4*)sx)[tid] = ((const float4*)&x[nb * IN_DIM])[tid];
    __syncthreads();

    // phase 1: z = lrelu(x @ W_ne + b_ne), 1024 outputs, 4/thread
#pragma unroll
    for (int r = 0; r < 4; r++) {
        int idx = tid + 256 * r;
        int n = idx >> 6, l = idx & 63;
        float acc = b_ne[l];
#pragma unroll
        for (int k = 0; k < IN_DIM; k++)
            acc = fmaf(sx[n][k], sWne[k * LATENT + l], acc);
        sz[n][l] = fmaxf(acc, 0.01f * acc);
    }
    __syncthreads();

    // phase 2: 4 latents per thread, float4 weight loads
    {
        const int n = tid >> 4;           // 0..15
        const int l0 = (tid & 15) * 4;    // latent group base
        float zi[4] = {0.f, 0.f, 0.f, 0.f};
        float zjb[4];
        {
            const float4 b4 = *(const float4*)&b_e1[l0];
            zjb[0] = b4.x; zjb[1] = b4.y; zjb[2] = b4.z; zjb[3] = b4.w;
        }
#pragma unroll
        for (int k4 = 0; k4 < LATENT / 4; k4++) {
            const float4 z4 = *(const float4*)&sz[n][k4 * 4];
            const float zk[4] = {z4.x, z4.y, z4.z, z4.w};
#pragma unroll
            for (int m = 0; m < 4; m++) {
                const int k = k4 * 4 + m;
                const float4 wa = *(const float4*)&sWa[k * LATENT + l0];
                const float4 wb = *(const float4*)&sWb[k * LATENT + l0];
                zi[0]  = fmaf(zk[m], wa.x, zi[0]);
                zi[1]  = fmaf(zk[m], wa.y, zi[1]);
                zi[2]  = fmaf(zk[m], wa.z, zi[2]);
                zi[3]  = fmaf(zk[m], wa.w, zi[3]);
                zjb[0] = fmaf(zk[m], wb.x, zjb[0]);
                zjb[1] = fmaf(zk[m], wb.y, zjb[1]);
                zjb[2] = fmaf(zk[m], wb.z, zjb[2]);
                zjb[3] = fmaf(zk[m], wb.w, zjb[3]);
            }
        }
        *(float4*)&szi[n][l0]  = make_float4(zi[0], zi[1], zi[2], zi[3]);
        *(float4*)&szjb[n][l0] = make_float4(zjb[0], zjb[1], zjb[2], zjb[3]);
        *(float4*)&g_zi[(nb + n) * LATENT + l0] =
            make_float4(zi[0], zi[1], zi[2], zi[3]);
#pragma unroll
        for (int m = 0; m < 4; m++)
            g_zbT[(size_t)(l0 + m) * N_NODES + nb + n] = zjb[m];
    }
    __syncthreads();

    // reductions: warp w handles nodes 2w, 2w+1
    const int wid = tid >> 5, lane = tid & 31;
    const float w1 = w_e2[lane], w2 = w_e2[lane + 32];
#pragma unroll
    for (int s = 0; s < 2; s++) {
        const int n = 2 * wid + s;
        float s1 = w1 * szi[n][lane]  + w2 * szi[n][lane + 32];
        float s2 = w1 * szjb[n][lane] + w2 * szjb[n][lane + 32];
#pragma unroll
        for (int off = 16; off > 0; off >>= 1) {
            s1 += __shfl_down_sync(0xffffffffu, s1, off);
            s2 += __shfl_down_sync(0xffffffffu, s2, off);
        }
        if (lane == 0) {
            g_aw2[nb + n] = 0.505f * s1;
            g_cw2[nb + n] = 0.505f * s2 + b_e2[0];
        }
    }
    if (blockIdx.x == 0 && tid < LATENT)
        g_ws[tid] = 0.495f * w_e2[tid];
}

// ---------------------------------------------------------------------------
// Kernel 2: 64x64 tile per block, 256 threads, 4x4 outputs/thread (R1 frame).
// Scalar math with abs folded into the FFMA operand modifier:
//   acc = fmaf(w, fabsf(a + b), acc)  ->  FADD ; FFMA R,Rw,|Rv|,Racc
// Zero alu-pipe instructions in the loop. 4 blocks/SM, grid 1024.
// logit(i,j) = aw2[i] + cw2[j] + sum_l ws[l] * |zi[i,l] + zjb[j,l]|
// out = (sigmoid(logit) + 1e-8) * exp(gumbel)
// ---------------------------------------------------------------------------
__global__ __launch_bounds__(256, 4) void edge_prob_kernel(
    const float* __restrict__ gumbel, float* __restrict__ out)
{
    extern __shared__ char smem_raw[];
    float* s_zi   = (float*)smem_raw;                    // [64][PADT] 17408B
    float* s_zjbT = (float*)(smem_raw + 17408);          // [64][PADT] 17408B
    float* s_ws   = (float*)(smem_raw + 34816);          // [64]         256B
    float* s_aw   = (float*)(smem_raw + 35072);          // [64]         256B
    float* s_cw   = (float*)(smem_raw + 35328);          // [64]         256B

    const int tid = threadIdx.x;
    const int ibase = blockIdx.y * 64;
    const int jbase = blockIdx.x * 64;

    // load phase (coalesced float4 from pre-laid-out globals)
#pragma unroll
    for (int t = tid; t < 1024; t += 256) {
        int r = t >> 4, c4 = (t & 15) * 4;
        *(float4*)&s_zi[r * PADT + c4] =
            *(const float4*)&g_zi[(size_t)(ibase + r) * LATENT + c4];
        *(float4*)&s_zjbT[r * PADT + c4] =
            *(const float4*)&g_zbT[(size_t)r * N_NODES + jbase + c4];
    }
    if (tid < 64) {
        s_ws[tid] = g_ws[tid];
        s_aw[tid] = g_aw2[ibase + tid];
        s_cw[tid] = g_cw2[jbase + tid];
    }
    __syncthreads();

    const int tx = tid & 15;   // j sub-tile
    const int ty = tid >> 4;   // i sub-tile

    float acc[4][4] = {};

#pragma unroll 4
    for (int lc = 0; lc < 16; lc++) {
        const float4 wv = *(const float4*)&s_ws[lc * 4];
        const float w[4] = {wv.x, wv.y, wv.z, wv.w};

        float a[4][4];   // [ii][lsub]
#pragma unroll
        for (int ii = 0; ii < 4; ii++) {
            const float4 t = *(const float4*)&s_zi[(ty * 4 + ii) * PADT + lc * 4];
            a[ii][0] = t.x; a[ii][1] = t.y; a[ii][2] = t.z; a[ii][3] = t.w;
        }
        float b[4][4];   // [lsub][jj]
#pragma unroll
        for (int u = 0; u < 4; u++) {
            const float4 t = *(const float4*)&s_zjbT[(lc * 4 + u) * PADT + tx * 4];
            b[u][0] = t.x; b[u][1] = t.y; b[u][2] = t.z; b[u][3] = t.w;
        }

#pragma unroll
        for (int u = 0; u < 4; u++) {
#pragma unroll
            for (int ii = 0; ii < 4; ii++) {
                const float ai = a[ii][u];
#pragma unroll
                for (int jj = 0; jj < 4; jj++) {
                    // plain fabsf -> folded as |operand| into the FFMA
                    acc[ii][jj] = fmaf(w[u], fabsf(ai + b[u][jj]), acc[ii][jj]);
                }
            }
        }
    }

    // epilogue
#pragma unroll
    for (int ii = 0; ii < 4; ii++) {
        const int i = ibase + ty * 4 + ii;
        const int j0 = jbase + tx * 4;
        const float base_i = s_aw[ty * 4 + ii];
        const size_t off = (size_t)i * N_NODES + j0;
        const float4 gv = *(const float4*)&gumbel[off];
        const float g4[4] = {gv.x, gv.y, gv.z, gv.w};
        float4 o;
        float* op = &o.x;
#pragma unroll
        for (int jj = 0; jj < 4; jj++) {
            float logit = acc[ii][jj] + base_i + s_cw[tx * 4 + jj];
            float e = __expf(-logit);
            float p = __fdividef(1.0f, 1.0f + e);
            op[jj] = (p + 1e-8f) * __expf(g4[jj]);
        }
        *(float4*)&out[off] = o;
    }
}

// ---------------------------------------------------------------------------
// Inputs (metadata order):
// 0:x [N,32] 1:in_adj [N,N](unused) 2:gumbel [N,N] 3:W_ne [32,64] 4:b_ne [64]
// 5:W_e1a [64,64] 6:W_e1b [64,64] 7:b_e1 [64] 8:w_e2 [64] 9:b_e2 []
// out: [N,N] float32
// ---------------------------------------------------------------------------
extern "C" void kernel_launch(void* const* d_in, const int* in_sizes, int n_in,
                              void* d_out, int out_size)
{
    const float* x      = (const float*)d_in[0];
    const float* gumbel = (const float*)d_in[2];
    const float* W_ne   = (const float*)d_in[3];
    const float* b_ne   = (const float*)d_in[4];
    const float* W_e1a  = (const float*)d_in[5];
    const float* W_e1b  = (const float*)d_in[6];
    const float* b_e1   = (const float*)d_in[7];
    const float* w_e2   = (const float*)d_in[8];
    const float* b_e2   = (const float*)d_in[9];
    float* out = (float*)d_out;

    node_precompute_kernel<<<N_NODES / 16, 256>>>(x, W_ne, b_ne, W_e1a, W_e1b,
                                                  b_e1, w_e2, b_e2);

    static bool attr_set = false;
    if (!attr_set) {
        cudaFuncSetAttribute(edge_prob_kernel,
                             cudaFuncAttributeMaxDynamicSharedMemorySize, 35584);
        attr_set = true;
    }
    dim3 grid(N_NODES / 64, N_NODES / 64);
    edge_prob_kernel<<<grid, 256, 35584>>>(gumbel, out);
}

// round 16
// speedup vs baseline: 1.3744x; 1.0010x over previous
#include <cuda_runtime.h>
#include <cstdint>

#define N_NODES 2048
#define IN_DIM 32
#define LATENT 64
#define PADT 68    // tile row stride (floats); 272B, 16B-aligned

// Scratch (__device__ globals: allocation-free rule)
__device__ float g_zi[N_NODES * LATENT];    // [n][l]
__device__ float g_zbT[LATENT * N_NODES];   // [l][n] transposed
__device__ float g_ws[LATENT];              // 0.495 * w
__device__ float g_aw2[N_NODES];            // 0.505 * dot(w, zi[i])
__device__ float g_cw2[N_NODES];            // 0.505 * dot(w, zjb[j]) + b_e2

// ---------------------------------------------------------------------------
// Kernel 1: per-node precompute, 8 nodes/block -> 256 blocks.
// Phase 2: 2 latents/thread over all 256 threads (256 fma/thread).
// ---------------------------------------------------------------------------
__global__ __launch_bounds__(256) void node_precompute_kernel(
    const float* __restrict__ x,
    const float* __restrict__ W_ne, const float* __restrict__ b_ne,
    const float* __restrict__ W_e1a, const float* __restrict__ W_e1b,
    const float* __restrict__ b_e1,
    const float* __restrict__ w_e2, const float* __restrict__ b_e2)
{
    __shared__ float sWne[IN_DIM * LATENT];    // 8KB
    __shared__ float sWa[LATENT * LATENT];     // 16KB
    __shared__ float sWb[LATENT * LATENT];     // 16KB
    __shared__ float sx[8][IN_DIM];
    __shared__ float sz[8][LATENT];
    __shared__ float szi[8][LATENT];
    __shared__ float szjb[8][LATENT];

    const int tid = threadIdx.x;
    const int nb = blockIdx.x * 8;

    for (int i = tid; i < IN_DIM * LATENT / 4; i += 256)
        ((float4*)sWne)[i] = ((const float4*)W_ne)[i];
    for (int i = tid; i < LATENT * LATENT / 4; i += 256) {
        ((float4*)sWa)[i] = ((const float4*)W_e1a)[i];
        ((float4*)sWb)[i] = ((const float4*)W_e1b)[i];
    }
    if (tid < 64)
        ((float4*)sx)[tid] = ((const float4*)&x[nb * IN_DIM])[tid];
    __syncthreads();

    // phase 1: z = lrelu(x @ W_ne + b_ne), 512 outputs, 2/thread
#pragma unroll
    for (int r = 0; r < 2; r++) {
        int idx = tid + 256 * r;
        int n = idx >> 6, l = idx & 63;
        float acc = b_ne[l];
#pragma unroll
        for (int k = 0; k < IN_DIM; k++)
            acc = fmaf(sx[n][k], sWne[k * LATENT + l], acc);
        sz[n][l] = fmaxf(acc, 0.01f * acc);
    }
    __syncthreads();

    // phase 2: 2 latents/thread; warp-uniform node (z broadcast)
    {
        const int n = tid >> 5;           // 0..7
        const int l0 = (tid & 31) * 2;    // 0,2,..,62
        float zi0 = 0.f, zi1 = 0.f;
        float zj0, zj1;
        {
            const float2 b2 = *(const float2*)&b_e1[l0];
            zj0 = b2.x; zj1 = b2.y;
        }
#pragma unroll
        for (int k4 = 0; k4 < LATENT / 4; k4++) {
            const float4 z4 = *(const float4*)&sz[n][k4 * 4];  // broadcast
            const float zk[4] = {z4.x, z4.y, z4.z, z4.w};
#pragma unroll
            for (int m = 0; m < 4; m++) {
                const int k = k4 * 4 + m;
                const float2 wa = *(const float2*)&sWa[k * LATENT + l0];
                const float2 wb = *(const float2*)&sWb[k * LATENT + l0];
                zi0 = fmaf(zk[m], wa.x, zi0);
                zi1 = fmaf(zk[m], wa.y, zi1);
                zj0 = fmaf(zk[m], wb.x, zj0);
                zj1 = fmaf(zk[m], wb.y, zj1);
            }
        }
        *(float2*)&szi[n][l0]  = make_float2(zi0, zi1);
        *(float2*)&szjb[n][l0] = make_float2(zj0, zj1);
        *(float2*)&g_zi[(nb + n) * LATENT + l0] = make_float2(zi0, zi1);
        g_zbT[(size_t)l0 * N_NODES + nb + n] = zj0;
        g_zbT[(size_t)(l0 + 1) * N_NODES + nb + n] = zj1;
    }
    __syncthreads();

    // reductions: warp w handles node w
    const int wid = tid >> 5, lane = tid & 31;
    const float w1 = w_e2[lane], w2 = w_e2[lane + 32];
    float s1 = w1 * szi[wid][lane]  + w2 * szi[wid][lane + 32];
    float s2 = w1 * szjb[wid][lane] + w2 * szjb[wid][lane + 32];
#pragma unroll
    for (int off = 16; off > 0; off >>= 1) {
        s1 += __shfl_down_sync(0xffffffffu, s1, off);
        s2 += __shfl_down_sync(0xffffffffu, s2, off);
    }
    if (lane == 0) {
        g_aw2[nb + wid] = 0.505f * s1;
        g_cw2[nb + wid] = 0.505f * s2 + b_e2[0];
    }
    if (blockIdx.x == 0 && tid < LATENT)
        g_ws[tid] = 0.495f * w_e2[tid];
}

// ---------------------------------------------------------------------------
// Kernel 2 (UNCHANGED from R15 — proven 26.0us): 64x64 tile, 256 threads,
// 4x4 outputs/thread, abs folded into FFMA operand modifier, 4 blocks/SM.
// logit(i,j) = aw2[i] + cw2[j] + sum_l ws[l] * |zi[i,l] + zjb[j,l]|
// out = (sigmoid(logit) + 1e-8) * exp(gumbel)
// ---------------------------------------------------------------------------
__global__ __launch_bounds__(256, 4) void edge_prob_kernel(
    const float* __restrict__ gumbel, float* __restrict__ out)
{
    extern __shared__ char smem_raw[];
    float* s_zi   = (float*)smem_raw;                    // [64][PADT] 17408B
    float* s_zjbT = (float*)(smem_raw + 17408);          // [64][PADT] 17408B
    float* s_ws   = (float*)(smem_raw + 34816);          // [64]         256B
    float* s_aw   = (float*)(smem_raw + 35072);          // [64]         256B
    float* s_cw   = (float*)(smem_raw + 35328);          // [64]         256B

    const int tid = threadIdx.x;
    const int ibase = blockIdx.y * 64;
    const int jbase = blockIdx.x * 64;

#pragma unroll
    for (int t = tid; t < 1024; t += 256) {
        int r = t >> 4, c4 = (t & 15) * 4;
        *(float4*)&s_zi[r * PADT + c4] =
            *(const float4*)&g_zi[(size_t)(ibase + r) * LATENT + c4];
        *(float4*)&s_zjbT[r * PADT + c4] =
            *(const float4*)&g_zbT[(size_t)r * N_NODES + jbase + c4];
    }
    if (tid < 64) {
        s_ws[tid] = g_ws[tid];
        s_aw[tid] = g_aw2[ibase + tid];
        s_cw[tid] = g_cw2[jbase + tid];
    }
    __syncthreads();

    const int tx = tid & 15;   // j sub-tile
    const int ty = tid >> 4;   // i sub-tile

    float acc[4][4] = {};

#pragma unroll 4
    for (int lc = 0; lc < 16; lc++) {
        const float4 wv = *(const float4*)&s_ws[lc * 4];
        const float w[4] = {wv.x, wv.y, wv.z, wv.w};

        float a[4][4];   // [ii][lsub]
#pragma unroll
        for (int ii = 0; ii < 4; ii++) {
            const float4 t = *(const float4*)&s_zi[(ty * 4 + ii) * PADT + lc * 4];
            a[ii][0] = t.x; a[ii][1] = t.y; a[ii][2] = t.z; a[ii][3] = t.w;
        }
        float b[4][4];   // [lsub][jj]
#pragma unroll
        for (int u = 0; u < 4; u++) {
            const float4 t = *(const float4*)&s_zjbT[(lc * 4 + u) * PADT + tx * 4];
            b[u][0] = t.x; b[u][1] = t.y; b[u][2] = t.z; b[u][3] = t.w;
        }

#pragma unroll
        for (int u = 0; u < 4; u++) {
#pragma unroll
            for (int ii = 0; ii < 4; ii++) {
                const float ai = a[ii][u];
#pragma unroll
                for (int jj = 0; jj < 4; jj++) {
                    // plain fabsf -> folded as |operand| into the FFMA
                    acc[ii][jj] = fmaf(w[u], fabsf(ai + b[u][jj]), acc[ii][jj]);
                }
            }
        }
    }

    // epilogue
#pragma unroll
    for (int ii = 0; ii < 4; ii++) {
        const int i = ibase + ty * 4 + ii;
        const int j0 = jbase + tx * 4;
        const float base_i = s_aw[ty * 4 + ii];
        const size_t off = (size_t)i * N_NODES + j0;
        const float4 gv = *(const float4*)&gumbel[off];
        const float g4[4] = {gv.x, gv.y, gv.z, gv.w};
        float4 o;
        float* op = &o.x;
#pragma unroll
        for (int jj = 0; jj < 4; jj++) {
            float logit = acc[ii][jj] + base_i + s_cw[tx * 4 + jj];
            float e = __expf(-logit);
            float p = __fdividef(1.0f, 1.0f + e);
            op[jj] = (p + 1e-8f) * __expf(g4[jj]);
        }
        *(float4*)&out[off] = o;
    }
}

// ---------------------------------------------------------------------------
// Inputs (metadata order):
// 0:x [N,32] 1:in_adj [N,N](unused) 2:gumbel [N,N] 3:W_ne [32,64] 4:b_ne [64]
// 5:W_e1a [64,64] 6:W_e1b [64,64] 7:b_e1 [64] 8:w_e2 [64] 9:b_e2 []
// out: [N,N] float32
// ---------------------------------------------------------------------------
extern "C" void kernel_launch(void* const* d_in, const int* in_sizes, int n_in,
                              void* d_out, int out_size)
{
    const float* x      = (const float*)d_in[0];
    const float* gumbel = (const float*)d_in[2];
    const float* W_ne   = (const float*)d_in[3];
    const float* b_ne   = (const float*)d_in[4];
    const float* W_e1a  = (const float*)d_in[5];
    const float* W_e1b  = (const float*)d_in[6];
    const float* b_e1   = (const float*)d_in[7];
    const float* w_e2   = (const float*)d_in[8];
    const float* b_e2   = (const float*)d_in[9];
    float* out = (float*)d_out;

    node_precompute_kernel<<<N_NODES / 8, 256>>>(x, W_ne, b_ne, W_e1a, W_e1b,
                                                 b_e1, w_e2, b_e2);

    static bool attr_set = false;
    if (!attr_set) {
        cudaFuncSetAttribute(edge_prob_kernel,
                             cudaFuncAttributeMaxDynamicSharedMemorySize, 35584);
        attr_set = true;
    }
    dim3 grid(N_NODES / 64, N_NODES / 64);
    edge_prob_kernel<<<grid, 256, 35584>>>(gumbel, out);
}